// round 17
// baseline (speedup 1.0000x reference)
#include <cuda_runtime.h>
#include <cstdint>

typedef unsigned long long ull;

#define BATCH 1024
#define TLEN  200
#define DDIM  128
#define HDIM  128
#define NXC   384
#define MROWS (BATCH * TLEN)
#define NGRP2 512

// compact x-projection (sorted-row-major) + perm/offsets
__device__ float g_xproj[(size_t)MROWS * NXC];
__device__ int   g_perm[BATCH];
__device__ int   g_coff[BATCH + 1];
// packed tf32 hi/lo W fragments (B operand): [3 ct][16 nf][16 ks][32 lane] uint4
__device__ uint4 g_wpack[3 * 16 * 16 * 32];

// ---------- packed f32x2 helpers ----------
__device__ __forceinline__ ull pack2(float x, float y) {
    ull r; asm("mov.b64 %0,{%1,%2};" : "=l"(r) : "f"(x), "f"(y)); return r;
}
__device__ __forceinline__ float2 unpack2(ull v) {
    float2 f; asm("mov.b64 {%0,%1},%2;" : "=f"(f.x), "=f"(f.y) : "l"(v)); return f;
}
__device__ __forceinline__ void ffma2(ull &d, ull a, ull b) {
    asm("fma.rn.f32x2 %0,%1,%2,%0;" : "+l"(d) : "l"(a), "l"(b));
}
__device__ __forceinline__ ull addf2(ull a, ull b) {
    ull r; asm("add.rn.f32x2 %0,%1,%2;" : "=l"(r) : "l"(a), "l"(b)); return r;
}
__device__ __forceinline__ float tanhap(float x) {
    float r; asm("tanh.approx.f32 %0,%1;" : "=f"(r) : "f"(x)); return r;
}
__device__ __forceinline__ float sigap(float x) {
    return fmaf(tanhap(0.5f * x), 0.5f, 0.5f);
}
__device__ __forceinline__ uint32_t tf32rna(float x) {
    uint32_t r; asm("cvt.rna.tf32.f32 %0, %1;" : "=r"(r) : "f"(x)); return r;
}
// mma.sync m16n8k8 tf32: D += A*B (acc in-place)
__device__ __forceinline__ void mma8(float* d, uint32_t a0, uint32_t a1, uint32_t a2, uint32_t a3,
                                     uint32_t b0, uint32_t b1) {
    asm volatile("mma.sync.aligned.m16n8k8.row.col.f32.tf32.tf32.f32 "
        "{%0,%1,%2,%3}, {%4,%5,%6,%7}, {%8,%9}, {%0,%1,%2,%3};"
        : "+f"(d[0]), "+f"(d[1]), "+f"(d[2]), "+f"(d[3])
        : "r"(a0), "r"(a1), "r"(a2), "r"(a3), "r"(b0), "r"(b1));
}

// =====================================================================
// Kernel 0: counting sort rows by seq_len DESC -> g_perm; exclusive
// prefix sum of sorted lengths -> g_coff.
// =====================================================================
__global__ void __launch_bounds__(1024) dien_sort_kernel(const int* __restrict__ seq)
{
    __shared__ int s[1024];
    __shared__ int sperm[1024];
    __shared__ int cnt[256];
    __shared__ int cur[256];
    __shared__ int buf[1024];
    const int tid = threadIdx.x;

    s[tid] = seq[tid];
    if (tid < 256) { cnt[tid] = 0; cur[tid] = 0; }
    __syncthreads();
    atomicAdd(&cnt[s[tid] & 255], 1);
    __syncthreads();
    if (tid < 256) buf[tid] = cnt[tid];
    __syncthreads();
    for (int off = 1; off < 256; off <<= 1) {
        int v = 0;
        if (tid < 256) { v = buf[tid]; if (tid + off < 256) v += buf[tid + off]; }
        __syncthreads();
        if (tid < 256) buf[tid] = v;
        __syncthreads();
    }
    {
        int v = s[tid] & 255;
        int start = buf[v] - cnt[v];
        int rank = atomicAdd(&cur[v], 1);
        sperm[start + rank] = tid;
    }
    __syncthreads();
    g_perm[tid] = sperm[tid];
    int sl = s[sperm[tid]];
    buf[tid] = sl;
    __syncthreads();
    for (int off = 1; off < 1024; off <<= 1) {
        int v = buf[tid] + ((tid >= off) ? buf[tid - off] : 0);
        __syncthreads();
        buf[tid] = v;
        __syncthreads();
    }
    g_coff[tid] = buf[tid] - sl;
    if (tid == 1023) g_coff[1024] = buf[1023];
}

// =====================================================================
// Kernel 0b: pack W as B-operand fragments (hi/lo tf32 split).
// =====================================================================
__global__ void __launch_bounds__(256) dien_prep_kernel(
    const float* __restrict__ Wg, const float* __restrict__ Wc)
{
    int idx = blockIdx.x * 256 + threadIdx.x;   // < 3*16*16*32 = 24576
    if (idx >= 24576) return;
    int lane = idx & 31, ks = (idx >> 5) & 15, nf = (idx >> 9) & 15, ct = idx >> 13;
    int tig = lane & 3, gid = lane >> 2;
    int n = ct * 128 + nf * 8 + gid;
    int k0 = ks * 8 + tig, k1 = k0 + 4;

    float w0 = (n < 256) ? Wg[k0 * 256 + n] : Wc[k0 * 128 + n - 256];
    float w1 = (n < 256) ? Wg[k1 * 256 + n] : Wc[k1 * 128 + n - 256];

    uint4 rec;
    rec.x = tf32rna(w0);
    rec.y = tf32rna(w1);
    rec.z = tf32rna(w0 - __uint_as_float(rec.x));
    rec.w = tf32rna(w1 - __uint_as_float(rec.y));
    g_wpack[idx] = rec;
}

// =====================================================================
// Phase 1 (unchanged R16): split-tf32 mma.sync xproj, 32-row warp tiles,
// column-split staged epilogue.
// =====================================================================
__global__ void __launch_bounds__(256, 1) dien_xproj_mma(
    const float* __restrict__ X,
    const float* __restrict__ bg, const float* __restrict__ bc)
{
    extern __shared__ char smraw[];
    float* Xs    = (float*)smraw;                    // 131072 B
    float* stage = (float*)(smraw + 131072);         // [256 row][72] = 73728 B
    float* sbias = (float*)(smraw + 131072 + 73728); // 384
    int* scoff   = (int*)((char*)sbias + 1536);      // 1025
    int* srcrow  = scoff + 1025;                     // 256

    const int tid  = threadIdx.x;
    const int lane = tid & 31;
    const int w    = tid >> 5;
    const int r0   = blockIdx.x * 256;

    const int total = g_coff[1024];
    if (r0 >= total) return;

    for (int i = tid; i < 1025; i += 256) scoff[i] = g_coff[i];
    for (int i = tid; i < 384; i += 256) sbias[i] = (i < 256) ? bg[i] : bc[i - 256];
    __syncthreads();
    {
        int vr = r0 + tid;
        int sr = -1;
        if (vr < total) {
            int lo = 0, hi = 1024;
            while (hi - lo > 1) { int mid = (lo + hi) >> 1; if (scoff[mid] <= vr) lo = mid; else hi = mid; }
            sr = g_perm[lo] * TLEN + (vr - scoff[lo]);
        }
        srcrow[tid] = sr;
    }
    __syncthreads();

    {
        const float4* X4 = (const float4*)X;
        for (int idx = tid; idx < 8192; idx += 256) {
            int row = idx >> 5, k4 = idx & 31;
            int sr = srcrow[row];
            float4 v = make_float4(0.f, 0.f, 0.f, 0.f);
            if (sr >= 0) v = X4[(size_t)sr * 32 + k4];
            int rt = row >> 4, r16 = row & 15;
            int gid = r16 & 7, half = r16 >> 3;
            #pragma unroll
            for (int j = 0; j < 4; j++) {
                int k = k4 * 4 + j;
                float x = (j == 0) ? v.x : (j == 1) ? v.y : (j == 2) ? v.z : v.w;
                int ks = k >> 3, kk = k & 7;
                int tg = kk & 3, kh = kk >> 2;
                Xs[((rt * 16 + ks) * 32 + gid * 4 + tg) * 4 + half + 2 * kh] = x;
            }
        }
    }
    __syncthreads();

    const float4* Xs4 = (const float4*)Xs;

    for (int round = 0; round < 3; round++) {
        float acc[2][16][4];
        #pragma unroll
        for (int mt = 0; mt < 2; mt++)
            #pragma unroll
            for (int nf = 0; nf < 16; nf++)
                #pragma unroll
                for (int i = 0; i < 4; i++) acc[mt][nf][i] = 0.f;

        const uint4* wp = g_wpack + ((size_t)round * 16 * 16) * 32 + lane;

        #pragma unroll 2
        for (int ks = 0; ks < 16; ks++) {
            uint32_t AH[2][4], AL[2][4];
            #pragma unroll
            for (int mt = 0; mt < 2; mt++) {
                float4 a = Xs4[((w * 2 + mt) * 16 + ks) * 32 + lane];
                float av[4] = {a.x, a.y, a.z, a.w};
                #pragma unroll
                for (int i = 0; i < 4; i++) {
                    uint32_t h = tf32rna(av[i]);
                    AH[mt][i] = h;
                    AL[mt][i] = tf32rna(av[i] - __uint_as_float(h));
                }
            }
            #pragma unroll
            for (int nf = 0; nf < 16; nf++) {
                uint4 b = __ldg(wp + ((size_t)nf * 16 + ks) * 32);
                mma8(acc[0][nf], AH[0][0], AH[0][1], AH[0][2], AH[0][3], b.x, b.y);
                mma8(acc[0][nf], AH[0][0], AH[0][1], AH[0][2], AH[0][3], b.z, b.w);
                mma8(acc[0][nf], AL[0][0], AL[0][1], AL[0][2], AL[0][3], b.x, b.y);
                mma8(acc[1][nf], AH[1][0], AH[1][1], AH[1][2], AH[1][3], b.x, b.y);
                mma8(acc[1][nf], AH[1][0], AH[1][1], AH[1][2], AH[1][3], b.z, b.w);
                mma8(acc[1][nf], AL[1][0], AL[1][1], AL[1][2], AL[1][3], b.x, b.y);
            }
        }

        #pragma unroll
        for (int p = 0; p < 2; p++) {
            #pragma unroll
            for (int mt = 0; mt < 2; mt++) {
                int row0 = w * 32 + mt * 16 + (lane >> 2);
                int row1 = row0 + 8;
                int cb = (lane & 3) * 2;
                #pragma unroll
                for (int nfl = 0; nfl < 8; nfl++) {
                    int nf = p * 8 + nfl;
                    int cg = nf * 8 + cb;
                    int lc = nfl * 8 + cb;
                    float b0 = sbias[round * 128 + cg];
                    float b1 = sbias[round * 128 + cg + 1];
                    *(float2*)&stage[row0 * 72 + lc] =
                        make_float2(acc[mt][nf][0] + b0, acc[mt][nf][1] + b1);
                    *(float2*)&stage[row1 * 72 + lc] =
                        make_float2(acc[mt][nf][2] + b0, acc[mt][nf][3] + b1);
                }
            }
            __syncthreads();
            for (int idx = tid; idx < 4096; idx += 256) {
                int row = idx >> 4, c4 = idx & 15;
                int vr = r0 + row;
                if (vr < total) {
                    const float* sp = stage + row * 72 + c4 * 4;
                    *(float4*)&g_xproj[(size_t)vr * NXC + round * 128 + p * 64 + c4 * 4] =
                        make_float4(sp[0], sp[1], sp[2], sp[3]);
                }
            }
            __syncthreads();
        }
    }
}

// =====================================================================
// Phase 2: 2-row k-parity GRU. 512 CTAs x 512 thr, sorted 2-row groups.
// f32x2 lanes = (k-even, k-odd). h / r*h stored SCALAR [row][128].
// Gate weights: 32 k-pair ull in regs (64 regs). Cand weights: k-pair
// ull in smem. ZERO dup movs. Epilogue: thread (jc, q<2) owns row q and
// keeps u/Ho in regs across segments.
// =====================================================================
__global__ void __launch_bounds__(512, 1) dien_gru_kernel(
    const float* __restrict__ Wg, const float* __restrict__ Wc,
    const int* __restrict__ seqlen, float* __restrict__ out)
{
    extern __shared__ char smraw[];
    ull*   whcP = (ull*)smraw;                    // [64 k2][128 jc]           65536 B
    float* hp   = (float*)(smraw + 65536);        // [2 row][128] scalar        1024 B
    float* rhp  = hp + 256;                       // [2 row][128] scalar        1024 B
    ull*   red  = (ull*)(smraw + 65536 + 2048);   // 2048 ull                  16384 B

    const int tid = threadIdx.x;
    const int jc  = tid & 127;
    const int q   = tid >> 7;            // k-split 0..3 (epi owners: q<2 -> row q)
    const int k0  = q * 32;

    // ---- cand weights packed (w[2k2], w[2k2+1]) ----
    for (int i = tid; i < 64 * 128; i += 512) {
        int k2 = i >> 7, j = i & 127;
        whcP[i] = pack2(Wc[(size_t)(128 + 2 * k2) * 128 + j],
                        Wc[(size_t)(128 + 2 * k2 + 1) * 128 + j]);
    }
    // ---- gate weights: 16+16 k-pair ull in regs ----
    ull wr2[16], wu2[16];
    #pragma unroll
    for (int i = 0; i < 16; i++) {
        wr2[i] = pack2(Wg[(size_t)(128 + k0 + 2 * i) * 256 + jc],
                       Wg[(size_t)(128 + k0 + 2 * i + 1) * 256 + jc]);
        wu2[i] = pack2(Wg[(size_t)(128 + k0 + 2 * i) * 256 + jc + 128],
                       Wg[(size_t)(128 + k0 + 2 * i + 1) * 256 + jc + 128]);
    }

    const int g = blockIdx.x;                      // 2-row group: sorted pos 2g, 2g+1
    const int maxseq = seqlen[g_perm[2 * g]];      // sorted desc
    const int pos = 2 * g + ((q < 2) ? q : 0);
    const int myrow = g_perm[pos];
    const int sq    = seqlen[myrow];
    const int cof   = g_coff[pos];

    if (tid < 256) hp[tid] = 0.f;
    __syncthreads();

    const float* xrow = g_xproj + (size_t)cof * NXC + jc;
    float* orow = out + (size_t)myrow * TLEN * HDIM + jc;

    const ulonglong2* h0v = (const ulonglong2*)(hp + k0);
    const ulonglong2* h1v = (const ulonglong2*)(hp + 128 + k0);
    const ulonglong2* r0v = (const ulonglong2*)(rhp + k0);
    const ulonglong2* r1v = (const ulonglong2*)(rhp + 128 + k0);
    const ull* wcb = whcP + (k0 >> 1) * 128 + jc;

    for (int t = 0; t < maxseq; t++) {
        // prefetch x-projections (epi threads only)
        float xr = 0.f, xu = 0.f, xc = 0.f;
        if (q < 2 && t < sq) {
            const float* p = xrow + (size_t)t * NXC;
            xr = p[0]; xu = p[128]; xc = p[256];
        }

        // ---- gate GEMV: 2 rows x 2 gates, k in [k0,k0+32), zero movs ----
        ull aR0 = 0, aR1 = 0, aU0 = 0, aU1 = 0;
        #pragma unroll
        for (int i = 0; i < 8; i++) {
            ulonglong2 a0 = h0v[i];      // broadcast
            ulonglong2 a1 = h1v[i];
            ull w0 = wr2[2 * i], w1 = wr2[2 * i + 1];
            ull v0 = wu2[2 * i], v1 = wu2[2 * i + 1];
            ffma2(aR0, a0.x, w0); ffma2(aR0, a0.y, w1);
            ffma2(aR1, a1.x, w0); ffma2(aR1, a1.y, w1);
            ffma2(aU0, a0.x, v0); ffma2(aU0, a0.y, v1);
            ffma2(aU1, a1.x, v0); ffma2(aU1, a1.y, v1);
        }
        {
            ull* st = red + q * 512 + jc;       // row stride 128, u offset 256
            st[0] = aR0; st[128] = aR1; st[256] = aU0; st[384] = aU1;
        }
        __syncthreads();

        // ---- gate epilogue (q<2): row q, col jc ----
        float r_g, u_g, Ho;
        if (q < 2) {
            const ull* rd = red + q * 128 + jc;     // q' stride 512
            ull zr = rd[0], zu = rd[256];
            #pragma unroll
            for (int qq = 1; qq < 4; qq++) {
                zr = addf2(zr, rd[qq * 512]);
                zu = addf2(zu, rd[qq * 512 + 256]);
            }
            float2 Zr = unpack2(zr), Zu = unpack2(zu);
            r_g = sigap(Zr.x + Zr.y + xr);
            u_g = sigap(Zu.x + Zu.y + xu);
            Ho = hp[q * 128 + jc];
            rhp[q * 128 + jc] = r_g * Ho;
        }
        __syncthreads();

        // ---- cand GEMV: 2 rows, k-parity, packed smem weights ----
        ull aC0 = 0, aC1 = 0;
        #pragma unroll
        for (int i = 0; i < 8; i++) {
            ull w0 = wcb[(2 * i) * 128];
            ull w1 = wcb[(2 * i + 1) * 128];
            ulonglong2 a0 = r0v[i];      // broadcast
            ulonglong2 a1 = r1v[i];
            ffma2(aC0, a0.x, w0); ffma2(aC0, a0.y, w1);
            ffma2(aC1, a1.x, w0); ffma2(aC1, a1.y, w1);
        }
        {
            ull* st = red + q * 256 + jc;
            st[0] = aC0; st[128] = aC1;
        }
        __syncthreads();

        // ---- cand epilogue + state update (q<2) ----
        if (q < 2) {
            const ull* rd = red + q * 128 + jc;     // q' stride 256
            ull zc = rd[0];
            #pragma unroll
            for (int qq = 1; qq < 4; qq++) zc = addf2(zc, rd[qq * 256]);
            float2 Zc = unpack2(zc);
            float c = tanhap(Zc.x + Zc.y + xc);
            float hn = fmaf(u_g, Ho - c, c);        // u*h + (1-u)*c
            bool v = t < sq;
            hp[q * 128 + jc] = v ? hn : Ho;
            if (v) orow[(size_t)t * HDIM] = hn;
        }
        __syncthreads();
    }

    // ---- tail zero-fill: out[row, t>=seq, :] = 0 ----
    #pragma unroll
    for (int rr = 0; rr < 2; rr++) {
        int row = g_perm[2 * g + rr];
        int s = seqlen[row];
        float* op = out + (size_t)row * TLEN * HDIM;
        for (int i = s * HDIM + tid; i < TLEN * HDIM; i += 512) op[i] = 0.f;
    }
}

// =====================================================================
extern "C" void kernel_launch(void* const* d_in, const int* in_sizes, int n_in,
                              void* d_out, int out_size)
{
    const float* X   = (const float*)d_in[0];
    const int*   seq = (const int*)  d_in[1];
    const float* Wg  = (const float*)d_in[2];
    const float* bg  = (const float*)d_in[3];
    const float* Wc  = (const float*)d_in[4];
    const float* bc  = (const float*)d_in[5];
    float* out = (float*)d_out;
    (void)in_sizes; (void)n_in; (void)out_size;

    const int SMEM_MMA = 131072 + 73728 + 1536 + 1025 * 4 + 256 * 4 + 256;  // ~211.8 KB
    const int SMEM2 = 65536 + 2048 + 16384;                                 // 83968 B
    cudaFuncSetAttribute(dien_xproj_mma, cudaFuncAttributeMaxDynamicSharedMemorySize, SMEM_MMA);
    cudaFuncSetAttribute(dien_gru_kernel, cudaFuncAttributeMaxDynamicSharedMemorySize, SMEM2);

    dien_sort_kernel<<<1, 1024>>>(seq);
    dien_prep_kernel<<<96, 256>>>(Wg, Wc);
    dien_xproj_mma<<<800, 256, SMEM_MMA>>>(X, bg, bc);
    dien_gru_kernel<<<NGRP2, 512, SMEM2>>>(Wg, Wc, seq, out);
}